// round 5
// baseline (speedup 1.0000x reference)
#include <cuda_runtime.h>
#include <math.h>

#define NT 512
#define NFEAT 1024
#define NCAT 1536
#define MEMSZ 16384
#define RSQRTNF 0.17677669529663689f
#define NBLK 148
#define NTHD 512
#define NTH (NBLK * NTHD)

// ---- output layout (float element offsets) ----
#define OUT_MEM    0
#define OUT_TMEM   8388608
#define OUT_FMEM   8404992
#define OUT_ARE    25182208
#define OUT_AIM    25198592
#define OUT_FREQ   25214976
#define OUT_RP     25215008
#define OUT_BIAS   26001440
#define OUT_FMEAN  26001952
#define OUT_AGRE   26002976
#define OUT_AGIM   26019360
#define OUT_FG     26035744
#define OUT_RPG    26035776

// ---- scratch (double-buffered per batch where rewritten) ----
__device__ __align__(16) float g_ux[32 * NFEAT];
__device__ __align__(16) float g_uzb[2][16 * NT];
__device__ __align__(16) float g_zbm[32 * NT];
__device__ __align__(16) float g_G[2][16 * NT];
__device__ __align__(16) float g_D[2][16 * NT];
__device__ __align__(16) float g_ct[2][16 * 32];
__device__ __align__(16) float g_st[2][16 * 32];
__device__ __align__(16) float g_tp2[32];
__device__ __align__(16) float g_dfr[2][32];
__device__ __align__(16) float g_agre[2][32 * NT];
__device__ __align__(16) float g_agim[2][32 * NT];
__device__ __align__(16) float g_fga[2][32];
__device__ __align__(16) float g_rgb[2][NCAT * NT];
__device__ float g_nrm[2][4];
__device__ float g_lr;
__device__ unsigned g_cnt;
__device__ volatile unsigned g_gen;

__device__ __forceinline__ float sgnf(float v) {
    return (v > 0.f) ? 1.f : ((v < 0.f) ? -1.f : 0.f);
}

// software grid barrier — all NBLK blocks must be co-resident (grid == SM count)
__device__ __forceinline__ void gsync() {
    __syncthreads();
    if (threadIdx.x == 0) {
        unsigned gen = g_gen;
        __threadfence();
        if (atomicAdd(&g_cnt, 1u) == NBLK - 1) {
            g_cnt = 0;
            __threadfence();
            g_gen = gen + 1;
        } else {
            while (g_gen == gen) __nanosleep(64);
            __threadfence();
        }
    }
    __syncthreads();
}

__device__ __forceinline__ void trig_one(float fq_f, float cfv, float tt,
                                         float* cv, float* sv, float* dfr) {
    double fq = (double)fq_f;
    double th = tanh(fq);
    double w = (double)cfv + 2.0 * th;
    double sg = 1.0 / (1.0 + exp(-w));
    double ph = (double)tt * (sg * 0.5);
    *cv = (float)cos(ph);
    *sv = (float)sin(ph);
    *dfr = (float)(0.5 * sg * (1.0 - sg) * 2.0 * (1.0 - th * th));
}

__device__ __forceinline__ void copy_unit(int u,
        const float* rp, const float* rpg, const float* are, const float* aim,
        const float* agre, const float* agim, const float* freq, const float* fg,
        const float* bias, const float* fmean, const float* z, const float* x,
        float dsn, float* out) {
    const int S_RP = NCAT * NT / 4;   // 196608
    const int S_AMP = 32 * NT / 4;    // 4096
    if (u < S_RP) { ((float4*)(out + OUT_RP))[u] = ((const float4*)rp)[u]; return; }
    u -= S_RP;
    if (u < S_RP) { ((float4*)(out + OUT_RPG))[u] = ((const float4*)rpg)[u]; return; }
    u -= S_RP;
    if (u < S_AMP) { ((float4*)(out + OUT_ARE))[u] = ((const float4*)are)[u]; return; }
    u -= S_AMP;
    if (u < S_AMP) { ((float4*)(out + OUT_AIM))[u] = ((const float4*)aim)[u]; return; }
    u -= S_AMP;
    if (u < S_AMP) { ((float4*)(out + OUT_AGRE))[u] = ((const float4*)agre)[u]; return; }
    u -= S_AMP;
    if (u < S_AMP) { ((float4*)(out + OUT_AGIM))[u] = ((const float4*)agim)[u]; return; }
    u -= S_AMP;
    if (u < 32) { out[OUT_FREQ + u] = freq[u]; return; }
    u -= 32;
    if (u < 32) { out[OUT_FG + u] = fg[u]; return; }
    u -= 32;
    if (u < NT) { out[OUT_BIAS + u] = (bias[u] * dsn + z[u]) / (dsn + 1.0f); return; }
    u -= NT;
    if (u < NFEAT) { out[OUT_FMEAN + u] = (fmean[u] * dsn + x[u]) / (dsn + 1.0f); return; }
}

// ================= side stream: big copies with inline row substitution =================
__global__ void k_bigcopy(const float* __restrict__ memory, const float* __restrict__ fmem,
                          const int* __restrict__ tmem,
                          const float* __restrict__ z, const float* __restrict__ x,
                          const int* __restrict__ tp, const int* __restrict__ dsp,
                          float* __restrict__ out) {
    const long long N1 = (long long)MEMSZ * NT / 4;
    const long long N2c = (long long)MEMSZ * NFEAT / 4;
    const long long N3c = MEMSZ / 4;
    long long u = (long long)blockIdx.x * 256 + threadIdx.x;
    int ds = *dsp;
    if (u < N1) {
        int k = (int)u;
        int row = (k * 4) >> 9;
        float4 v;
        if (row == ds) v = *(const float4*)(z + ((k * 4) & 511));
        else           v = ((const float4*)memory)[k];
        ((float4*)(out + OUT_MEM))[k] = v;
    } else if (u < N1 + N2c) {
        int k = (int)(u - N1);
        int row = (k * 4) >> 10;
        float4 v;
        if (row == ds) v = *(const float4*)(x + ((k * 4) & 1023));
        else           v = ((const float4*)fmem)[k];
        ((float4*)(out + OUT_FMEM))[k] = v;
    } else if (u < N1 + N2c + N3c) {
        int k = (int)(u - N1 - N2c);
        int4 iv = ((const int4*)tmem)[k];
        float4 f = make_float4((float)iv.x, (float)iv.y, (float)iv.z, (float)iv.w);
        if ((ds >> 2) == k) ((float*)&f)[ds & 3] = (float)(*tp);
        ((float4*)(out + OUT_TMEM))[k] = f;
    }
}

// ================= the mega kernel =================
__global__ void __launch_bounds__(NTHD, 1)
k_mega(const int* __restrict__ tp, const int* __restrict__ dsp, const int* __restrict__ ts,
       const float* __restrict__ x, const float* __restrict__ z,
       const float* __restrict__ memory, const int* __restrict__ tmem,
       const float* __restrict__ fmem,
       const float* __restrict__ are_in, const float* __restrict__ aim_in,
       const float* __restrict__ freq_in, const float* __restrict__ cf,
       const float* __restrict__ rp_in, const float* __restrict__ fmean,
       const float* __restrict__ bias,
       const float* __restrict__ agre_in, const float* __restrict__ agim_in,
       const float* __restrict__ fg_in, const float* __restrict__ rpg_in,
       float* __restrict__ out) {
    __shared__ float sbuf[8448];
    int bid = blockIdx.x, tid = threadIdx.x;
    int gtid = bid * NTHD + tid;
    int ds = *dsp;
    float dsn = (float)(ds + 1);

    // ======== P0: param copies + gather + batch-0 eval + zero accumulators ========
    if (gtid == 0) g_lr = (float)pow(0.977, (double)(ds + 1));
    {
        const int PCU = NCAT * NT / 4 * 2 + 32 * NT / 4 * 4 + 64 + NT + NFEAT;
        for (int u = gtid; u < PCU; u += NTH)
            copy_unit(u, rp_in, rpg_in, are_in, aim_in, agre_in, agim_in,
                      freq_in, fg_in, bias, fmean, z, x, dsn, out);
    }
    if (bid < 32) {
        int s = bid;
        int idx = ts[s];
        g_zbm[s * NT + tid] = (idx == ds) ? z[tid] : memory[idx * NT + tid];
        for (int jj = tid; jj < NFEAT; jj += NTHD) {
            float xv = (idx == ds) ? x[jj] : fmem[idx * NFEAT + jj];
            float fm = (fmean[jj] * dsn + x[jj]) / (dsn + 1.0f);
            g_ux[s * NFEAT + jj] = xv - fm;
        }
        if (tid == 0) {
            float tv = (idx == ds) ? (float)(*tp) : (float)tmem[idx];
            g_tp2[s] = 6.2831853071795864769f * tv;
        }
    } else if (bid >= 64 && bid < 80) {
        // batch-0 eval for sample i = bid-64, from INPUT params
        int i = bid - 64;
        int idx = ts[i];
        float tv = (idx == ds) ? (float)(*tp) : (float)tmem[idx];
        float tt = 6.2831853071795864769f * tv;
        float* sc = sbuf;
        float* ss = sbuf + 32;
        if (tid < 32) {
            float cv, sv, dfr;
            trig_one(freq_in[tid], cf[tid], tt, &cv, &sv, &dfr);
            sc[tid] = cv; ss[tid] = sv;
            g_ct[0][i * 32 + tid] = cv;
            g_st[0][i * 32 + tid] = sv;
            if (i == 0) g_dfr[0][tid] = dfr;
        }
        __syncthreads();
        float acc = 0.f;
#pragma unroll
        for (int f = 0; f < 32; f++)
            acc += sc[f] * are_in[f * NT + tid] - ss[f] * aim_in[f * NT + tid];
        g_uzb[0][i * NT + tid] = acc * RSQRTNF;
    } else if (bid == 140) {
        if (tid < 8) ((float*)g_nrm)[tid] = 0.f;
        if (tid >= 32 && tid < 96) ((float*)g_fga)[tid - 32] = 0.f;
    }
    gsync();

    for (int b = 0; b < 2; b++) {
        const float* freq_p = b ? (out + OUT_FREQ) : freq_in;
        const float* are_p  = b ? (out + OUT_ARE)  : are_in;
        const float* aim_p  = b ? (out + OUT_AIM)  : aim_in;
        const float* rp_p   = b ? (out + OUT_RP)   : rp_in;

        // ======== N2: [eval b1] + r GEMM + G/D  (blocks 0..63) ========
        if (bid < 64) {
            int ig = bid >> 4, tc = bid & 15;
            float* smu = sbuf;            // 4 * 1536
            float* sct = sbuf + 6144;     // 4 * 32
            float* sst = sbuf + 6272;     // 4 * 32
            float* red = sbuf + 6400;     // 4 * 512
            for (int k = tid; k < 4 * NFEAT; k += NTHD) {
                int s = k >> 10, j = k & 1023;
                smu[s * NCAT + j] = g_ux[(b * 16 + ig * 4 + s) * NFEAT + j];
            }
            if (b == 1) {
                if (tid < 128) {
                    int s = tid >> 5, f = tid & 31;
                    float tt = g_tp2[16 + ig * 4 + s];
                    float cv, sv, dfr;
                    trig_one(freq_p[f], cf[f], tt, &cv, &sv, &dfr);
                    sct[s * 32 + f] = cv; sst[s * 32 + f] = sv;
                    if (tc == 0) {
                        g_ct[1][(ig * 4 + s) * 32 + f] = cv;
                        g_st[1][(ig * 4 + s) * 32 + f] = sv;
                    }
                    if (bid == 0 && s == 0) g_dfr[1][f] = dfr;
                }
                __syncthreads();
#pragma unroll
                for (int s = 0; s < 4; s++) {
                    float acc = 0.f;
#pragma unroll
                    for (int f = 0; f < 32; f++)
                        acc += sct[s * 32 + f] * are_p[f * NT + tid]
                             - sst[s * 32 + f] * aim_p[f * NT + tid];
                    acc *= RSQRTNF;
                    smu[s * NCAT + NFEAT + tid] = acc;
                    if (tc == 0) g_uzb[1][(ig * 4 + s) * NT + tid] = acc;
                }
            } else {
                for (int k = tid; k < 4 * NT; k += NTHD) {
                    int s = k >> 9, t2 = k & 511;
                    smu[s * NCAT + NFEAT + t2] = g_uzb[0][(ig * 4 + s) * NT + t2];
                }
            }
            __syncthreads();
            // GEMM: js = tid>>5 covers 96 j's, q = tid&31 -> t = tc*32+q
            {
                int js = tid >> 5, q = tid & 31;
                int t = tc * 32 + q;
                const float* rcol = rp_p + t;
                float a0 = 0.f, a1 = 0.f, a2 = 0.f, a3 = 0.f;
                int j0 = js * 96;
#pragma unroll 6
                for (int j = j0; j < j0 + 96; j += 4) {
                    float r0 = rcol[(size_t)j * NT];
                    float r1 = rcol[(size_t)(j + 1) * NT];
                    float r2 = rcol[(size_t)(j + 2) * NT];
                    float r3 = rcol[(size_t)(j + 3) * NT];
                    float4 u0 = *(const float4*)&smu[0 * NCAT + j];
                    float4 u1 = *(const float4*)&smu[1 * NCAT + j];
                    float4 u2 = *(const float4*)&smu[2 * NCAT + j];
                    float4 u3 = *(const float4*)&smu[3 * NCAT + j];
                    a0 += u0.x * r0 + u0.y * r1 + u0.z * r2 + u0.w * r3;
                    a1 += u1.x * r0 + u1.y * r1 + u1.z * r2 + u1.w * r3;
                    a2 += u2.x * r0 + u2.y * r1 + u2.z * r2 + u2.w * r3;
                    a3 += u3.x * r0 + u3.y * r1 + u3.z * r2 + u3.w * r3;
                }
                red[0 * 512 + js * 32 + q] = a0;
                red[1 * 512 + js * 32 + q] = a1;
                red[2 * 512 + js * 32 + q] = a2;
                red[3 * 512 + js * 32 + q] = a3;
            }
            __syncthreads();
            if (tid < 128) {
                int s = tid >> 5, q = tid & 31;
                int t = tc * 32 + q;
                float rt = 0.f;
#pragma unroll
                for (int js = 0; js < 16; js++) rt += red[s * 512 + js * 32 + q];
                float bv = (bias[t] * dsn + z[t]) / (dsn + 1.0f);
                float zh = smu[s * NCAT + NFEAT + t] + bv;
                float zb = g_zbm[(b * 16 + ig * 4 + s) * NT + t];
                float ar = fabsf(rt) + 1.0f;
                float z2 = zh + rt / ar;
                int i = ig * 4 + s;
                g_G[b][i * NT + t] = (-0.03f / 16.0f) * sgnf(zb - z2) / (ar * ar);
                g_D[b][i * NT + t] = (-1.0f / 16.0f) * sgnf(zb - zh);
            }
        }
        gsync();

        // ======== N3: backD+ampgrad (units 0..511) | rg (units 512..895) ========
        for (int unit = bid; unit < 896; unit += NBLK) {
            __syncthreads();
            if (unit < 512) {
                int t = unit;
                float* srz = sbuf;          // 512
                float* sD  = sbuf + 512;    // 16
                float* stt = sbuf + 528;    // 16
                srz[tid] = rp_p[(size_t)(NFEAT + t) * NT + tid];
                if (tid < 16) stt[tid] = g_tp2[b * 16 + tid];
                __syncthreads();
                int lane = tid & 31, w = tid >> 5;
                float acc = 0.f;
#pragma unroll 4
                for (int tq = lane; tq < NT; tq += 32)
                    acc += g_G[b][w * NT + tq] * srz[tq];
#pragma unroll
                for (int o = 16; o > 0; o >>= 1)
                    acc += __shfl_down_sync(0xffffffffu, acc, o);
                if (lane == 0) sD[w] = g_D[b][w * NT + t] + acc;
                __syncthreads();
                if (tid < 32) {
                    int f = tid;
                    float are = are_p[f * NT + t], aim = aim_p[f * NT + t];
                    float sre = 0.f, sim = 0.f, sf = 0.f;
#pragma unroll
                    for (int i = 0; i < 16; i++) {
                        float d = sD[i];
                        float c = g_ct[b][i * 32 + f];
                        float s = g_st[b][i * 32 + f];
                        sre += d * c;
                        sim -= d * s;
                        sf += d * (-s * are - c * aim) * stt[i];
                    }
                    float aa = sqrtf(are * are + aim * aim);
                    float reg = 0.01f / (2.0f * aa * sqrtf(aa));
                    float agre = sre * RSQRTNF + are * reg;
                    float agim = sim * RSQRTNF + aim * reg;
                    g_agre[b][f * NT + t] = agre;
                    g_agim[b][f * NT + t] = agim;
                    atomicAdd(&g_fga[b][f], sf);
                    float nrm = agre * agre + agim * agim;
#pragma unroll
                    for (int o = 16; o > 0; o >>= 1)
                        nrm += __shfl_down_sync(0xffffffffu, nrm, o);
                    if (f == 0) atomicAdd(&g_nrm[b][0], nrm);
                }
            } else {
                float* su  = sbuf;          // 16*4
                float* swr = sbuf + 64;     // 16
                int j0 = (unit - 512) * 4;
                if (tid < 64) {
                    int i = tid >> 2, jj = tid & 3;
                    int j = j0 + jj;
                    float v = (j < NFEAT) ? g_ux[(b * 16 + i) * NFEAT + j]
                                          : g_uzb[b][i * NT + (j - NFEAT)];
                    su[i * 4 + jj] = v;
                }
                __syncthreads();
                float a0 = 0.f, a1 = 0.f, a2 = 0.f, a3 = 0.f;
#pragma unroll
                for (int i = 0; i < 16; i++) {
                    float gv = g_G[b][i * NT + tid];
                    a0 += su[i * 4 + 0] * gv;
                    a1 += su[i * 4 + 1] * gv;
                    a2 += su[i * 4 + 2] * gv;
                    a3 += su[i * 4 + 3] * gv;
                }
                g_rgb[b][(j0 + 0) * NT + tid] = a0;
                g_rgb[b][(j0 + 1) * NT + tid] = a1;
                g_rgb[b][(j0 + 2) * NT + tid] = a2;
                g_rgb[b][(j0 + 3) * NT + tid] = a3;
                float loc = a0 * a0 + a1 * a1 + a2 * a2 + a3 * a3;
#pragma unroll
                for (int o = 16; o > 0; o >>= 1)
                    loc += __shfl_down_sync(0xffffffffu, loc, o);
                if ((tid & 31) == 0) swr[tid >> 5] = loc;
                __syncthreads();
                if (tid < 16) {
                    loc = swr[tid];
#pragma unroll
                    for (int o = 8; o > 0; o >>= 1)
                        loc += __shfl_down_sync(0x0000ffffu, loc, o);
                    if (tid == 0) atomicAdd(&g_nrm[b][2], loc);
                }
            }
        }
        gsync();

        // ======== update ========
        {
            const int NRP4 = NCAT * NT / 4;
            const int NAMP4 = 32 * NT / 4;
            float lr = g_lr;
            float rn = sqrtf(__ldcg(&g_nrm[b][2])) + 1.0f;
            float an = sqrtf(__ldcg(&g_nrm[b][0])) + 1.0f;
            for (int idx = gtid; idx < NRP4 + NAMP4; idx += NTH) {
                if (idx < NRP4) {
                    float4 mo = ((float4*)(out + OUT_RPG))[idx];
                    float4 gr = ((const float4*)g_rgb[b])[idx];
                    float4 pv = ((float4*)(out + OUT_RP))[idx];
                    mo.x = mo.x * 0.85f + gr.x / rn;  pv.x -= mo.x * lr;
                    mo.y = mo.y * 0.85f + gr.y / rn;  pv.y -= mo.y * lr;
                    mo.z = mo.z * 0.85f + gr.z / rn;  pv.z -= mo.z * lr;
                    mo.w = mo.w * 0.85f + gr.w / rn;  pv.w -= mo.w * lr;
                    ((float4*)(out + OUT_RPG))[idx] = mo;
                    ((float4*)(out + OUT_RP))[idx] = pv;
                } else {
                    int k = idx - NRP4;
                    float4 mo = ((float4*)(out + OUT_AGRE))[k];
                    float4 gr = ((const float4*)g_agre[b])[k];
                    float4 pv = ((float4*)(out + OUT_ARE))[k];
                    mo.x = mo.x * 0.85f + gr.x / an;  pv.x -= mo.x * lr;
                    mo.y = mo.y * 0.85f + gr.y / an;  pv.y -= mo.y * lr;
                    mo.z = mo.z * 0.85f + gr.z / an;  pv.z -= mo.z * lr;
                    mo.w = mo.w * 0.85f + gr.w / an;  pv.w -= mo.w * lr;
                    ((float4*)(out + OUT_AGRE))[k] = mo;
                    ((float4*)(out + OUT_ARE))[k] = pv;
                    float4 mi = ((float4*)(out + OUT_AGIM))[k];
                    float4 gi = ((const float4*)g_agim[b])[k];
                    float4 pi = ((float4*)(out + OUT_AIM))[k];
                    mi.x = mi.x * 0.85f + gi.x / an;  pi.x -= mi.x * lr;
                    mi.y = mi.y * 0.85f + gi.y / an;  pi.y -= mi.y * lr;
                    mi.z = mi.z * 0.85f + gi.z / an;  pi.z -= mi.z * lr;
                    mi.w = mi.w * 0.85f + gi.w / an;  pi.w -= mi.w * lr;
                    ((float4*)(out + OUT_AGIM))[k] = mi;
                    ((float4*)(out + OUT_AIM))[k] = pi;
                }
            }
            if (bid == 0 && tid < 32) {
                float fgv = (__ldcg(&g_fga[b][tid]) * RSQRTNF) * __ldcg(&g_dfr[b][tid]);
                float n = fgv * fgv;
#pragma unroll
                for (int o = 16; o > 0; o >>= 1)
                    n += __shfl_xor_sync(0xffffffffu, n, o);
                float fn = sqrtf(n) + 1.0f;
                float m = out[OUT_FG + tid] * 0.85f + fgv / fn;
                out[OUT_FG + tid] = m;
                out[OUT_FREQ + tid] -= m * lr;
            }
        }
        if (b == 0) gsync();
    }
}

extern "C" void kernel_launch(void* const* d_in, const int* in_sizes, int n_in,
                              void* d_out, int out_size) {
    const int*   t_p    = (const int*)d_in[0];
    const int*   ds_p   = (const int*)d_in[1];
    const int*   ts     = (const int*)d_in[2];
    const float* x      = (const float*)d_in[3];
    const float* z      = (const float*)d_in[4];
    const float* memory = (const float*)d_in[5];
    const int*   tmem   = (const int*)d_in[6];
    const float* fmem   = (const float*)d_in[7];
    const float* amp_re = (const float*)d_in[8];
    const float* amp_im = (const float*)d_in[9];
    const float* freq   = (const float*)d_in[10];
    const float* cfreq  = (const float*)d_in[11];
    const float* rp     = (const float*)d_in[12];
    const float* fmean  = (const float*)d_in[13];
    const float* bias   = (const float*)d_in[14];
    const float* agre   = (const float*)d_in[15];
    const float* agim   = (const float*)d_in[16];
    const float* fg     = (const float*)d_in[17];
    const float* rpg    = (const float*)d_in[18];
    float* out = (float*)d_out;

    static cudaStream_t s1 = 0;
    static cudaEvent_t e0 = 0, e1 = 0;
    if (!s1) {
        cudaStreamCreateWithFlags(&s1, cudaStreamNonBlocking);
        cudaEventCreateWithFlags(&e0, cudaEventDisableTiming);
        cudaEventCreateWithFlags(&e1, cudaEventDisableTiming);
    }

    // ---- fork: big copies on side stream ----
    cudaEventRecord(e0, 0);
    cudaStreamWaitEvent(s1, e0, 0);
    {
        const long long total4 = (long long)MEMSZ * NT / 4 + (long long)MEMSZ * NFEAT / 4 + MEMSZ / 4;
        int blocks = (int)((total4 + 255) / 256);
        k_bigcopy<<<blocks, 256, 0, s1>>>(memory, fmem, tmem, z, x, t_p, ds_p, out);
    }
    cudaEventRecord(e1, s1);

    // ---- main chain: ONE kernel ----
    k_mega<<<NBLK, NTHD>>>(t_p, ds_p, ts, x, z, memory, tmem, fmem,
                           amp_re, amp_im, freq, cfreq, rp, fmean, bias,
                           agre, agim, fg, rpg, out);

    // ---- join ----
    cudaStreamWaitEvent(0, e1, 0);
    (void)in_sizes; (void)n_in; (void)out_size;
}